// round 2
// baseline (speedup 1.0000x reference)
#include <cuda_runtime.h>
#include <cstddef>

#define TT 1024
#define BB 4096

typedef unsigned long long ull;

__device__ __forceinline__ ull ffma2(ull a, ull b, ull c) {
    ull d;
    asm("fma.rn.f32x2 %0, %1, %2, %3;" : "=l"(d) : "l"(a), "l"(b), "l"(c));
    return d;
}
__device__ __forceinline__ ull fadd2(ull a, ull b) {
    ull d;
    asm("add.rn.f32x2 %0, %1, %2;" : "=l"(d) : "l"(a), "l"(b));
    return d;
}
__device__ __forceinline__ ull pack2(float lo, float hi) {
    ull d;
    asm("mov.b64 %0, {%1, %2};" : "=l"(d) : "f"(lo), "f"(hi));
    return d;
}
__device__ __forceinline__ float2 unpack2(ull v) {
    float2 f;
    asm("mov.b64 {%0, %1}, %2;" : "=f"(f.x), "=f"(f.y) : "l"(v));
    return f;
}
__device__ __forceinline__ float tanh_fast(float v) {
    float r;
    asm("tanh.approx.f32 %0, %1;" : "=f"(r) : "f"(v));
    return r;
}
__device__ __forceinline__ float sig_fast(float v) {
    return fmaf(0.5f, tanh_fast(0.5f * v), 0.5f);
}

// Row-pair packed dot: w = f32x2 entries (wa[j], wb[j]) in SMEM (16B aligned,
// even length 2*C), st = dup-packed states (v,v) in registers. bias in a0.
template <int C>
__device__ __forceinline__ ull dot2(const ull* __restrict__ w, const ull* st, ull bias) {
    ull a0 = bias, a1 = 0ull;
    const ulonglong2* w2 = reinterpret_cast<const ulonglong2*>(w);
#pragma unroll
    for (int i = 0; i < C; ++i) {
        ulonglong2 ww = w2[i];
        a0 = ffma2(ww.x, st[2 * i], a0);
        a1 = ffma2(ww.y, st[2 * i + 1], a1);
    }
    return fadd2(a0, a1);
}

// Load C chunks (2 dup states each) from state array laid out [buf][chunk][32][2].
template <int C>
__device__ __forceinline__ void ldstate(ull* dst, const ull* base) {
#pragma unroll
    for (int i = 0; i < C; ++i) {
        ulonglong2 v = *reinterpret_cast<const ulonglong2*>(base + i * 64);
        dst[2 * i] = v.x;
        dst[2 * i + 1] = v.y;
    }
}

__global__ __launch_bounds__(512, 1) void gru_fused(
    const float* __restrict__ x,
    const float* __restrict__ wih0, const float* __restrict__ whh0,
    const float* __restrict__ bih0, const float* __restrict__ bhh0,
    const float* __restrict__ wih1, const float* __restrict__ whh1,
    const float* __restrict__ bih1, const float* __restrict__ bhh1,
    const float* __restrict__ wih2, const float* __restrict__ whh2,
    const float* __restrict__ bih2, const float* __restrict__ bhh2,
    float* __restrict__ out)
{
    // ---- packed weights (f32x2 row pairs), all 16B aligned, even row strides
    __shared__ __align__(16) ull Wrz0[15 * 22];  // unit u: (r_u,z_u); [x5,pad,h15,pad]
    __shared__ __align__(16) ull Wxn0[8 * 6];    // pair p: xn rows (2p,2p+1); [x5,pad]
    __shared__ __align__(16) ull Whn0[8 * 16];   // pair p: hn rows; [h15,pad]
    __shared__ __align__(16) ull Wrz1[10 * 26];  // [h0:15,pad,h1:10]
    __shared__ __align__(16) ull Wxn1[5 * 16];   // [h0:15,pad]
    __shared__ __align__(16) ull Whn1[5 * 10];   // [h1:10]
    __shared__ __align__(16) ull Wrz2[2 * 12];   // [h1:10,h2:2]
    __shared__ __align__(16) ull Wxn2[1 * 10];   // [h1:10]
    __shared__ __align__(16) ull Whn2[1 * 2];    // [h2:2]
    __shared__ __align__(16) ull Brz0[15], Bxn0[8], Bhn0[8];
    __shared__ __align__(16) ull Brz1[10], Bxn1[5], Bhn1[5];
    __shared__ __align__(16) ull Brz2[2], Bxn2[1], Bhn2[1];
    // ---- dup-packed state, double buffered: ull[buf][chunk][32 lanes][2]
    __shared__ __align__(16) ull s_h0q[2 * 8 * 32 * 2];  // 16 slots (15 + zero pad)
    __shared__ __align__(16) ull s_h1q[2 * 5 * 32 * 2];  // 10 slots
    __shared__ __align__(16) ull s_h2q[2 * 1 * 32 * 2];  // 2 slots
    __shared__ __align__(16) ull s_xq[2 * 3 * 32 * 2];   // 6 slots (5 + zero pad)
    // ---- gate pre-activation buffers (single buffered; fenced by barriers)
    __shared__ __align__(16) ull grz0[15 * 32], gxn0[8 * 32], ghn0[8 * 32];
    __shared__ __align__(16) ull grz1[10 * 32], gxn1[5 * 32], ghn1[5 * 32];
    __shared__ __align__(16) ull grz2[2 * 32], gxn2[32], ghn2[32];

    const int tid = threadIdx.x;
    const int lane = tid & 31;
    const int w = tid >> 5;
    const int blk = blockIdx.x;

    // ================= init: zero states, pack weights =================
    for (int i = tid; i < 2 * 8 * 32 * 2; i += 512) s_h0q[i] = 0ull;
    for (int i = tid; i < 2 * 5 * 32 * 2; i += 512) s_h1q[i] = 0ull;
    for (int i = tid; i < 2 * 1 * 32 * 2; i += 512) s_h2q[i] = 0ull;
    for (int i = tid; i < 2 * 3 * 32 * 2; i += 512) s_xq[i] = 0ull;

    for (int idx = tid; idx < 15 * 22; idx += 512) {
        int u = idx / 22, j = idx % 22;
        float lo = 0.f, hi = 0.f;
        if (j < 5)              { lo = wih0[u * 5 + j];        hi = wih0[(15 + u) * 5 + j]; }
        else if (j >= 6 && j < 21) { int jj = j - 6; lo = whh0[u * 15 + jj]; hi = whh0[(15 + u) * 15 + jj]; }
        Wrz0[idx] = pack2(lo, hi);
    }
    for (int idx = tid; idx < 8 * 6; idx += 512) {
        int p = idx / 6, j = idx % 6, a = 2 * p, b = 2 * p + 1;
        float lo = 0.f, hi = 0.f;
        if (j < 5) { lo = wih0[(30 + a) * 5 + j]; hi = (b < 15) ? wih0[(30 + b) * 5 + j] : 0.f; }
        Wxn0[idx] = pack2(lo, hi);
    }
    for (int idx = tid; idx < 8 * 16; idx += 512) {
        int p = idx / 16, j = idx % 16, a = 2 * p, b = 2 * p + 1;
        float lo = 0.f, hi = 0.f;
        if (j < 15) { lo = whh0[(30 + a) * 15 + j]; hi = (b < 15) ? whh0[(30 + b) * 15 + j] : 0.f; }
        Whn0[idx] = pack2(lo, hi);
    }
    for (int idx = tid; idx < 10 * 26; idx += 512) {
        int u = idx / 26, j = idx % 26;
        float lo = 0.f, hi = 0.f;
        if (j < 15)      { lo = wih1[u * 15 + j];       hi = wih1[(10 + u) * 15 + j]; }
        else if (j >= 16) { int jj = j - 16; lo = whh1[u * 10 + jj]; hi = whh1[(10 + u) * 10 + jj]; }
        Wrz1[idx] = pack2(lo, hi);
    }
    for (int idx = tid; idx < 5 * 16; idx += 512) {
        int p = idx / 16, j = idx % 16, a = 2 * p, b = 2 * p + 1;
        float lo = 0.f, hi = 0.f;
        if (j < 15) { lo = wih1[(20 + a) * 15 + j]; hi = wih1[(20 + b) * 15 + j]; }
        Wxn1[idx] = pack2(lo, hi);
    }
    for (int idx = tid; idx < 5 * 10; idx += 512) {
        int p = idx / 10, j = idx % 10, a = 2 * p, b = 2 * p + 1;
        Whn1[idx] = pack2(whh1[(20 + a) * 10 + j], whh1[(20 + b) * 10 + j]);
    }
    for (int idx = tid; idx < 2 * 12; idx += 512) {
        int u = idx / 12, j = idx % 12;
        float lo, hi;
        if (j < 10) { lo = wih2[u * 10 + j]; hi = wih2[(2 + u) * 10 + j]; }
        else        { int jj = j - 10; lo = whh2[u * 2 + jj]; hi = whh2[(2 + u) * 2 + jj]; }
        Wrz2[idx] = pack2(lo, hi);
    }
    for (int idx = tid; idx < 10; idx += 512)
        Wxn2[idx] = pack2(wih2[4 * 10 + idx], wih2[5 * 10 + idx]);
    if (tid < 2) Whn2[tid] = pack2(whh2[4 * 2 + tid], whh2[5 * 2 + tid]);

    if (tid < 15) Brz0[tid] = pack2(bih0[tid] + bhh0[tid], bih0[15 + tid] + bhh0[15 + tid]);
    if (tid < 8) {
        int a = 2 * tid, b = 2 * tid + 1;
        Bxn0[tid] = pack2(bih0[30 + a], (b < 15) ? bih0[30 + b] : 0.f);
        Bhn0[tid] = pack2(bhh0[30 + a], (b < 15) ? bhh0[30 + b] : 0.f);
    }
    if (tid < 10) Brz1[tid] = pack2(bih1[tid] + bhh1[tid], bih1[10 + tid] + bhh1[10 + tid]);
    if (tid < 5) {
        Bxn1[tid] = pack2(bih1[20 + 2 * tid], bih1[20 + 2 * tid + 1]);
        Bhn1[tid] = pack2(bhh1[20 + 2 * tid], bhh1[20 + 2 * tid + 1]);
    }
    if (tid < 2) Brz2[tid] = pack2(bih2[tid] + bhh2[tid], bih2[2 + tid] + bhh2[2 + tid]);
    if (tid == 0) { Bxn2[0] = pack2(bih2[4], bih2[5]); Bhn2[0] = pack2(bhh2[4], bhh2[5]); }
    __syncthreads();

    // load x[0] into buffer 0 (dup-packed)
    if (tid < 160) {
        int e = tid / 5, i = tid % 5;
        float v = x[(size_t)blk * 160 + tid];
        s_xq[(i >> 1) * 64 + e * 2 + (i & 1)] = pack2(v, v);
    }
    __syncthreads();

    const auto lof = [](ull v) -> float { return unpack2(v).x; };

    // =================== skewed pipeline main loop ===================
    for (int k = 0; k < TT + 2; ++k) {
        const int bi = k & 1;
        const int bo = bi ^ 1;
        const bool act0 = (k < TT);
        const bool act1 = (k >= 1 && k <= TT);
        const bool act2 = (k >= 2);

        // x[k+1] prefetch by warps 5..9
        const int xt = tid - 160;
        const bool pf = (k + 1 < TT) && (xt >= 0) && (xt < 160);
        float xpre = 0.f;
        if (pf) xpre = x[(size_t)(k + 1) * (BB * 5) + (size_t)blk * 160 + xt];

        // -------- phase 1: gate pre-activations --------
        if (w < 5) {                               // rz0, 3 unit-pairs each
            if (act0) {
                ull st[22];
                ldstate<3>(st, s_xq + bi * 192 + lane * 2);
                ldstate<8>(st + 6, s_h0q + bo * 512 + lane * 2);
#pragma unroll
                for (int p = 0; p < 3; ++p) {
                    int u = w * 3 + p;
                    grz0[u * 32 + lane] = dot2<11>(Wrz0 + u * 22, st, Brz0[u]);
                }
            }
        } else if (w == 5) {                       // xn0, 8 pairs
            if (act0) {
                ull st[6];
                ldstate<3>(st, s_xq + bi * 192 + lane * 2);
#pragma unroll
                for (int p = 0; p < 8; ++p)
                    gxn0[p * 32 + lane] = dot2<3>(Wxn0 + p * 6, st, Bxn0[p]);
            }
        } else if (w < 8) {                        // hn0, 4 pairs each
            if (act0) {
                ull st[16];
                ldstate<8>(st, s_h0q + bo * 512 + lane * 2);
                int p0 = (w - 6) * 4;
#pragma unroll
                for (int p = 0; p < 4; ++p)
                    ghn0[(p0 + p) * 32 + lane] = dot2<8>(Whn0 + (p0 + p) * 16, st, Bhn0[p0 + p]);
            }
        } else if (w < 13) {                       // rz1, 2 unit-pairs each
            if (act1) {
                ull st[26];
                ldstate<8>(st, s_h0q + bo * 512 + lane * 2);
                ldstate<5>(st + 16, s_h1q + bi * 320 + lane * 2);
#pragma unroll
                for (int p = 0; p < 2; ++p) {
                    int u = (w - 8) * 2 + p;
                    grz1[u * 32 + lane] = dot2<13>(Wrz1 + u * 26, st, Brz1[u]);
                }
            }
        } else if (w == 13) {                      // xn1 pairs 0..3
            if (act1) {
                ull st[16];
                ldstate<8>(st, s_h0q + bo * 512 + lane * 2);
#pragma unroll
                for (int p = 0; p < 4; ++p)
                    gxn1[p * 32 + lane] = dot2<8>(Wxn1 + p * 16, st, Bxn1[p]);
            }
        } else if (w == 14) {                      // hn1 pairs 0..4
            if (act1) {
                ull st[10];
                ldstate<5>(st, s_h1q + bi * 320 + lane * 2);
#pragma unroll
                for (int p = 0; p < 5; ++p)
                    ghn1[p * 32 + lane] = dot2<5>(Whn1 + p * 10, st, Bhn1[p]);
            }
        } else {                                   // w15: xn1 pair 4 + all L2
            if (act1) {
                ull st[16];
                ldstate<8>(st, s_h0q + bo * 512 + lane * 2);
                gxn1[4 * 32 + lane] = dot2<8>(Wxn1 + 4 * 16, st, Bxn1[4]);
            }
            if (act2) {
                ull st2[12];
                ldstate<5>(st2, s_h1q + bi * 320 + lane * 2);
                ldstate<1>(st2 + 10, s_h2q + bo * 64 + lane * 2);
#pragma unroll
                for (int u = 0; u < 2; ++u)
                    grz2[u * 32 + lane] = dot2<6>(Wrz2 + u * 12, st2, Brz2[u]);
                gxn2[lane] = dot2<5>(Wxn2, st2, Bxn2[0]);
                ghn2[lane] = dot2<1>(Whn2, st2 + 10, Bhn2[0]);
            }
        }

        // stage next x into other buffer (read next iter, fenced by end barrier)
        if (pf) {
            int e = xt / 5, i = xt % 5;
            s_xq[bo * 192 + (i >> 1) * 64 + e * 2 + (i & 1)] = pack2(xpre, xpre);
        }

        __syncthreads();

        // -------- phase 2: activations + state update --------
        auto do_unit = [&](int u) {
            if (u < 15) {
                if (act0) {
                    float2 rz = unpack2(grz0[u * 32 + lane]);
                    float2 xp = unpack2(gxn0[(u >> 1) * 32 + lane]);
                    float2 hp2 = unpack2(ghn0[(u >> 1) * 32 + lane]);
                    float xn = (u & 1) ? xp.y : xp.x;
                    float hn = (u & 1) ? hp2.y : hp2.x;
                    float hprev = lof(s_h0q[bo * 512 + (u >> 1) * 64 + lane * 2 + (u & 1)]);
                    float r = sig_fast(rz.x), z = sig_fast(rz.y);
                    float n = tanh_fast(fmaf(r, hn, xn));
                    float hnew = fmaf(z, hprev - n, n);
                    s_h0q[bi * 512 + (u >> 1) * 64 + lane * 2 + (u & 1)] = pack2(hnew, hnew);
                }
            } else if (u < 25) {
                if (act1) {
                    int uu = u - 15;
                    float2 rz = unpack2(grz1[uu * 32 + lane]);
                    float2 xp = unpack2(gxn1[(uu >> 1) * 32 + lane]);
                    float2 hp2 = unpack2(ghn1[(uu >> 1) * 32 + lane]);
                    float xn = (uu & 1) ? xp.y : xp.x;
                    float hn = (uu & 1) ? hp2.y : hp2.x;
                    float hprev = lof(s_h1q[bi * 320 + (uu >> 1) * 64 + lane * 2 + (uu & 1)]);
                    float r = sig_fast(rz.x), z = sig_fast(rz.y);
                    float n = tanh_fast(fmaf(r, hn, xn));
                    float hnew = fmaf(z, hprev - n, n);
                    s_h1q[bo * 320 + (uu >> 1) * 64 + lane * 2 + (uu & 1)] = pack2(hnew, hnew);
                }
            } else {
                if (act2) {
                    int uu = u - 25;
                    float2 rz = unpack2(grz2[uu * 32 + lane]);
                    float2 xp = unpack2(gxn2[lane]);
                    float2 hp2 = unpack2(ghn2[lane]);
                    float xn = uu ? xp.y : xp.x;
                    float hn = uu ? hp2.y : hp2.x;
                    float hprev = lof(s_h2q[bo * 64 + lane * 2 + uu]);
                    float r = sig_fast(rz.x), z = sig_fast(rz.y);
                    float n = tanh_fast(fmaf(r, hn, xn));
                    float hnew = fmaf(z, hprev - n, n);
                    s_h2q[bi * 64 + lane * 2 + uu] = pack2(hnew, hnew);
                    out[(size_t)(k - 2) * (BB * 2) + (size_t)(blk * 32 + lane) * 2 + uu] = hnew;
                }
            }
        };
        do_unit(w);
        if (w >= 5) do_unit(w + 11);

        __syncthreads();
    }
}

extern "C" void kernel_launch(void* const* d_in, const int* in_sizes, int n_in,
                              void* d_out, int out_size) {
    (void)in_sizes; (void)n_in; (void)out_size;
    gru_fused<<<BB / 32, 512>>>(
        (const float*)d_in[0],
        (const float*)d_in[1], (const float*)d_in[2],
        (const float*)d_in[3], (const float*)d_in[4],
        (const float*)d_in[5], (const float*)d_in[6],
        (const float*)d_in[7], (const float*)d_in[8],
        (const float*)d_in[9], (const float*)d_in[10],
        (const float*)d_in[11], (const float*)d_in[12],
        (float*)d_out);
}

// round 5
// speedup vs baseline: 1.1660x; 1.1660x over previous
#include <cuda_runtime.h>
#include <cstddef>

#define TT 1024
#define BB 4096

typedef unsigned long long ull;

// ---------------- packed weight layout (ull = f32x2 pair) ----------------
// L0 jobs p=0..7 (units a=2p, b=2p+1; p=7 single):  base = p*68
//   +0  RZA[20]  (r_a,z_a) over [x(5), h0(15)]
//   +20 RZB[20]
//   +40 XN[6]    (n_a,n_b) over x(5) + pad
//   +46 HN[16]   (n_a,n_b) over h0(15) + pad
//   +62 B[4]     brz_a, brz_b, bxn, bhn      (66..67 pad)
// L1 jobs q=0..4 (a=2q,b=2q+1):  base = 544 + q*82
//   +0 RZA[26] over [h0(15), h1(10), pad]; +26 RZB[26]; +52 XN[16] over h0+pad;
//   +68 HN[10] over h1; +78 B[4]
// L2 job: base = 954
//   +0 RZA[12] over [h1(10), h2(2)]; +12 RZB[12]; +24 XN[10]; +34 HN[2]; +36 B[4]
// total 994 ull
#define L0BASE 0
#define L1BASE 544
#define L2BASE 954
#define NPACK 994

__device__ ull g_pack[1024];
__constant__ ull CW[1024];

__device__ __forceinline__ ull ffma2(ull a, ull b, ull c) {
    ull d;
    asm("fma.rn.f32x2 %0, %1, %2, %3;" : "=l"(d) : "l"(a), "l"(b), "l"(c));
    return d;
}
__device__ __forceinline__ ull fadd2(ull a, ull b) {
    ull d;
    asm("add.rn.f32x2 %0, %1, %2;" : "=l"(d) : "l"(a), "l"(b));
    return d;
}
__device__ __forceinline__ ull pack2(float lo, float hi) {
    ull d;
    asm("mov.b64 %0, {%1, %2};" : "=l"(d) : "f"(lo), "f"(hi));
    return d;
}
__device__ __forceinline__ float2 unpack2(ull v) {
    float2 f;
    asm("mov.b64 {%0, %1}, %2;" : "=f"(f.x), "=f"(f.y) : "l"(v));
    return f;
}
__device__ __forceinline__ float tanh_fast(float v) {
    float r;
    asm("tanh.approx.f32 %0, %1;" : "=f"(r) : "f"(v));
    return r;
}
__device__ __forceinline__ float sig_fast(float v) {
    return fmaf(0.5f, tanh_fast(0.5f * v), 0.5f);
}
__device__ __forceinline__ ull cvta_const(const void* p) {
    ull r;
    asm("cvta.to.const.u64 %0, %1;" : "=l"(r) : "l"(p));
    return r;
}
__device__ __forceinline__ ulonglong2 ldc2(ull caddr) {
    ulonglong2 r;
    asm("ld.const.v2.u64 {%0, %1}, [%2];" : "=l"(r.x), "=l"(r.y) : "l"(caddr));
    return r;
}

// shared-memory packed dot (uniform LDS.128 weight loads, broadcast)
template <int C>
__device__ __forceinline__ ull dots(const ull* __restrict__ w, const ull* st, ull bias) {
    ull a0 = bias, a1 = 0ull;
    const ulonglong2* w2 = reinterpret_cast<const ulonglong2*>(w);
#pragma unroll
    for (int i = 0; i < C / 2; ++i) {
        ulonglong2 ww = w2[i];
        a0 = ffma2(ww.x, st[2 * i], a0);
        a1 = ffma2(ww.y, st[2 * i + 1], a1);
    }
    return fadd2(a0, a1);
}
// constant-memory packed dot (LDC.128 via const port)
template <int C>
__device__ __forceinline__ ull dotc(ull cbase, const ull* st, ull bias) {
    ull a0 = bias, a1 = 0ull;
#pragma unroll
    for (int i = 0; i < C / 2; ++i) {
        ulonglong2 ww = ldc2(cbase + 16u * i);
        a0 = ffma2(ww.x, st[2 * i], a0);
        a1 = ffma2(ww.y, st[2 * i + 1], a1);
    }
    return fadd2(a0, a1);
}

// ---------------- pack kernel ----------------
__global__ void pack_weights(
    const float* __restrict__ wih0, const float* __restrict__ whh0,
    const float* __restrict__ bih0, const float* __restrict__ bhh0,
    const float* __restrict__ wih1, const float* __restrict__ whh1,
    const float* __restrict__ bih1, const float* __restrict__ bhh1,
    const float* __restrict__ wih2, const float* __restrict__ whh2,
    const float* __restrict__ bih2, const float* __restrict__ bhh2)
{
    int i = blockIdx.x * blockDim.x + threadIdx.x;
    if (i >= NPACK) return;
    float lo = 0.f, hi = 0.f;
    if (i < L1BASE) {
        int p = i / 68, r = i % 68;
        int a = 2 * p, b = 2 * p + 1;
        bool hb = (b < 15);
        if (r < 20) {
            int j = r;
            if (j < 5) { lo = wih0[a * 5 + j]; hi = wih0[(15 + a) * 5 + j]; }
            else       { int jj = j - 5; lo = whh0[a * 15 + jj]; hi = whh0[(15 + a) * 15 + jj]; }
        } else if (r < 40) {
            int j = r - 20;
            if (hb) {
                if (j < 5) { lo = wih0[b * 5 + j]; hi = wih0[(15 + b) * 5 + j]; }
                else       { int jj = j - 5; lo = whh0[b * 15 + jj]; hi = whh0[(15 + b) * 15 + jj]; }
            }
        } else if (r < 46) {
            int j = r - 40;
            if (j < 5) { lo = wih0[(30 + a) * 5 + j]; hi = hb ? wih0[(30 + b) * 5 + j] : 0.f; }
        } else if (r < 62) {
            int j = r - 46;
            if (j < 15) { lo = whh0[(30 + a) * 15 + j]; hi = hb ? whh0[(30 + b) * 15 + j] : 0.f; }
        } else if (r == 62) { lo = bih0[a] + bhh0[a]; hi = bih0[15 + a] + bhh0[15 + a]; }
        else if (r == 63) { if (hb) { lo = bih0[b] + bhh0[b]; hi = bih0[15 + b] + bhh0[15 + b]; } }
        else if (r == 64) { lo = bih0[30 + a]; hi = hb ? bih0[30 + b] : 0.f; }
        else if (r == 65) { lo = bhh0[30 + a]; hi = hb ? bhh0[30 + b] : 0.f; }
    } else if (i < L2BASE) {
        int t = i - L1BASE;
        int q = t / 82, r = t % 82;
        int a = 2 * q, b = 2 * q + 1;
        if (r < 26) {
            int j = r;
            if (j < 15)      { lo = wih1[a * 15 + j]; hi = wih1[(10 + a) * 15 + j]; }
            else if (j < 25) { int jj = j - 15; lo = whh1[a * 10 + jj]; hi = whh1[(10 + a) * 10 + jj]; }
        } else if (r < 52) {
            int j = r - 26;
            if (j < 15)      { lo = wih1[b * 15 + j]; hi = wih1[(10 + b) * 15 + j]; }
            else if (j < 25) { int jj = j - 15; lo = whh1[b * 10 + jj]; hi = whh1[(10 + b) * 10 + jj]; }
        } else if (r < 68) {
            int j = r - 52;
            if (j < 15) { lo = wih1[(20 + a) * 15 + j]; hi = wih1[(20 + b) * 15 + j]; }
        } else if (r < 78) {
            int j = r - 68;
            lo = whh1[(20 + a) * 10 + j]; hi = whh1[(20 + b) * 10 + j];
        } else if (r == 78) { lo = bih1[a] + bhh1[a]; hi = bih1[10 + a] + bhh1[10 + a]; }
        else if (r == 79) { lo = bih1[b] + bhh1[b]; hi = bih1[10 + b] + bhh1[10 + b]; }
        else if (r == 80) { lo = bih1[20 + a]; hi = bih1[20 + b]; }
        else              { lo = bhh1[20 + a]; hi = bhh1[20 + b]; }
    } else {
        int r = i - L2BASE;
        if (r < 12) {
            int j = r;
            if (j < 10) { lo = wih2[0 * 10 + j]; hi = wih2[2 * 10 + j]; }
            else        { int jj = j - 10; lo = whh2[0 * 2 + jj]; hi = whh2[2 * 2 + jj]; }
        } else if (r < 24) {
            int j = r - 12;
            if (j < 10) { lo = wih2[1 * 10 + j]; hi = wih2[3 * 10 + j]; }
            else        { int jj = j - 10; lo = whh2[1 * 2 + jj]; hi = whh2[3 * 2 + jj]; }
        } else if (r < 34) {
            int j = r - 24;
            lo = wih2[4 * 10 + j]; hi = wih2[5 * 10 + j];
        } else if (r < 36) {
            int j = r - 34;
            lo = whh2[4 * 2 + j]; hi = whh2[5 * 2 + j];
        } else if (r == 36) { lo = bih2[0] + bhh2[0]; hi = bih2[2] + bhh2[2]; }
        else if (r == 37) { lo = bih2[1] + bhh2[1]; hi = bih2[3] + bhh2[3]; }
        else if (r == 38) { lo = bih2[4]; hi = bih2[5]; }
        else              { lo = bhh2[4]; hi = bhh2[5]; }
    }
    ull v;
    asm("mov.b64 %0, {%1, %2};" : "=l"(v) : "f"(lo), "f"(hi));
    g_pack[i] = v;
}

// ---------------- main kernel ----------------
// grid 128, 512 threads = 16 warps per CTA of 32 batch elements.
// Skewed pipeline, 1 barrier/step: L0 computes h0[k], L1 h1[k-1], L2 h2[k-2].
__global__ __launch_bounds__(512, 1) void gru_fused(
    const float* __restrict__ x, const ull* __restrict__ gp,
    float* __restrict__ out)
{
    __shared__ __align__(16) ull sW0[544];          // L0 weights (LDS port)
    __shared__ __align__(16) float s_x[2][32][12];  // x, cols 5..11 zero
    __shared__ __align__(16) float s_h0[2][32][20]; // h0, cols 15..19 zero
    __shared__ __align__(16) float s_h1[2][32][12]; // h1, cols 10..11 zero
    __shared__ __align__(16) float s_h2[2][32][4];  // h2, cols 2..3 zero

    const int tid = threadIdx.x;
    const int lane = tid & 31;
    const int w = tid >> 5;
    const int blk = blockIdx.x;

    for (int i = tid; i < 544; i += 512) sW0[i] = gp[i];
    for (int i = tid; i < 2 * 32 * 20; i += 512) (&s_h0[0][0][0])[i] = 0.f;
    for (int i = tid; i < 2 * 32 * 12; i += 512) (&s_h1[0][0][0])[i] = 0.f;
    for (int i = tid; i < 2 * 32 * 12; i += 512) (&s_x[0][0][0])[i] = 0.f;
    for (int i = tid; i < 2 * 32 * 4; i += 512) (&s_h2[0][0][0])[i] = 0.f;
    if (tid < 160) s_x[0][tid / 5][tid % 5] = x[(size_t)blk * 160 + tid];
    __syncthreads();

    // job dispatch: SMSP (w&3) balanced
    int jt, ji = 0;
    switch (w) {
        case 0:  jt = 1; ji = 0; break;
        case 1:  jt = 1; ji = 2; break;
        case 2:  jt = 1; ji = 4; break;
        case 3:  jt = 2; break;
        case 4:  jt = 1; ji = 1; break;
        case 5:  jt = 1; ji = 3; break;
        case 6:  jt = 0; ji = 2; break;
        case 7:  jt = 0; ji = 4; break;
        case 8:  jt = 0; ji = 0; break;
        case 9:  jt = 0; ji = 1; break;
        case 10: jt = 0; ji = 3; break;
        case 11: jt = 0; ji = 5; break;
        case 12: jt = 3; ji = 0; break;
        case 13: jt = 3; ji = 1; break;
        case 14: jt = 0; ji = 7; break;
        case 15: jt = 0; ji = 6; break;
    }

    const ull* W0 = nullptr;
    ull cb = 0;
    ull b_rza = 0, b_rzb = 0, b_xn = 0, b_hn = 0;
    if (jt == 0) {
        W0 = sW0 + ji * 68;
        b_rza = W0[62]; b_rzb = W0[63]; b_xn = W0[64]; b_hn = W0[65];
    } else if (jt == 1) {
        int off = L1BASE + ji * 82;
        cb = cvta_const(&CW[off]);
        b_rza = CW[off + 78]; b_rzb = CW[off + 79];
        b_xn = CW[off + 80]; b_hn = CW[off + 81];
    } else if (jt == 2) {
        cb = cvta_const(&CW[L2BASE]);
        b_rza = CW[L2BASE + 36]; b_rzb = CW[L2BASE + 37];
        b_xn = CW[L2BASE + 38]; b_hn = CW[L2BASE + 39];
    }

    for (int k = 0; k < TT + 2; ++k) {
        const int bi = k & 1;
        const int bo = bi ^ 1;

        if (jt == 0) {
            if (k < TT) {
                const int a = 2 * ji;
                const bool pair = (ji < 7);
                float xr[8], hr[16];
                const float4* xp4 = reinterpret_cast<const float4*>(&s_x[bi][lane][0]);
                const float4* hp4 = reinterpret_cast<const float4*>(&s_h0[bi][lane][0]);
#pragma unroll
                for (int i = 0; i < 2; ++i) {
                    float4 v = xp4[i];
                    xr[4 * i] = v.x; xr[4 * i + 1] = v.y; xr[4 * i + 2] = v.z; xr[4 * i + 3] = v.w;
                }
#pragma unroll
                for (int i = 0; i < 4; ++i) {
                    float4 v = hp4[i];
                    hr[4 * i] = v.x; hr[4 * i + 1] = v.y; hr[4 * i + 2] = v.z; hr[4 * i + 3] = v.w;
                }
                ull st[21];
#pragma unroll
                for (int j = 0; j < 5; ++j) st[j] = pack2(xr[j], xr[j]);
#pragma unroll
                for (int j = 0; j < 16; ++j) st[5 + j] = pack2(hr[j], hr[j]);
                ull arz = dots<20>(W0, st, b_rza);
                ull brz = 0ull;
                if (pair) brz = dots<20>(W0 + 20, st, b_rzb);
                ull xn = dots<6>(W0 + 40, st, b_xn);
                ull hn = dots<16>(W0 + 46, st + 5, b_hn);
                float2 RZ = unpack2(arz), XN = unpack2(xn), HN = unpack2(hn);
                {
                    float r = sig_fast(RZ.x), z = sig_fast(RZ.y);
                    float n = tanh_fast(fmaf(r, HN.x, XN.x));
                    s_h0[bo][lane][a] = fmaf(z, hr[a] - n, n);
                }
                if (pair) {
                    float2 RZb = unpack2(brz);
                    float r = sig_fast(RZb.x), z = sig_fast(RZb.y);
                    float n = tanh_fast(fmaf(r, HN.y, XN.y));
                    s_h0[bo][lane][a + 1] = fmaf(z, hr[a + 1] - n, n);
                }
            }
        } else if (jt == 1) {
            if (k >= 1 && k <= TT) {
                const int a = 2 * ji;
                float h0r[16], h1r[12];
                const float4* hp4 = reinterpret_cast<const float4*>(&s_h0[bi][lane][0]);
                const float4* gp4 = reinterpret_cast<const float4*>(&s_h1[bi][lane][0]);
#pragma unroll
                for (int i = 0; i < 4; ++i) {
                    float4 v = hp4[i];
                    h0r[4 * i] = v.x; h0r[4 * i + 1] = v.y; h0r[4 * i + 2] = v.z; h0r[4 * i + 3] = v.w;
                }
#pragma unroll
                for (int i = 0; i < 3; ++i) {
                    float4 v = gp4[i];
                    h1r[4 * i] = v.x; h1r[4 * i + 1] = v.y; h1r[4 * i + 2] = v.z; h1r[4 * i + 3] = v.w;
                }
                ull st[26];
#pragma unroll
                for (int j = 0; j < 15; ++j) st[j] = pack2(h0r[j], h0r[j]);
#pragma unroll
                for (int j = 0; j < 10; ++j) st[15 + j] = pack2(h1r[j], h1r[j]);
                st[25] = 0ull;
                ull arz = dotc<26>(cb, st, b_rza);
                ull brz = dotc<26>(cb + 26 * 8, st, b_rzb);
                ull xn = dotc<16>(cb + 52 * 8, st, b_xn);
                ull hn = dotc<10>(cb + 68 * 8, st + 15, b_hn);
                float2 RZ = unpack2(arz), RZb = unpack2(brz), XN = unpack2(xn), HN = unpack2(hn);
                {
                    float r = sig_fast(RZ.x), z = sig_fast(RZ.y);
                    float n = tanh_fast(fmaf(r, HN.x, XN.x));
                    s_h1[bo][lane][a] = fmaf(z, h1r[a] - n, n);
                }
                {
                    float r = sig_fast(RZb.x), z = sig_fast(RZb.y);
                    float n = tanh_fast(fmaf(r, HN.y, XN.y));
                    s_h1[bo][lane][a + 1] = fmaf(z, h1r[a + 1] - n, n);
                }
            }
        } else if (jt == 2) {
            if (k >= 2) {
                float h1r[12];
                const float4* gp4 = reinterpret_cast<const float4*>(&s_h1[bi][lane][0]);
#pragma unroll
                for (int i = 0; i < 3; ++i) {
                    float4 v = gp4[i];
                    h1r[4 * i] = v.x; h1r[4 * i + 1] = v.y; h1r[4 * i + 2] = v.z; h1r[4 * i + 3] = v.w;
                }
                float2 h2v = *reinterpret_cast<const float2*>(&s_h2[bi][lane][0]);
                ull st[12];
#pragma unroll
                for (int j = 0; j < 10; ++j) st[j] = pack2(h1r[j], h1r[j]);
                st[10] = pack2(h2v.x, h2v.x);
                st[11] = pack2(h2v.y, h2v.y);
                ull arz = dotc<12>(cb, st, b_rza);
                ull brz = dotc<12>(cb + 12 * 8, st, b_rzb);
                ull xn = dotc<10>(cb + 24 * 8, st, b_xn);
                ull hn = dotc<2>(cb + 34 * 8, st + 10, b_hn);
                float2 RZ = unpack2(arz), RZb = unpack2(brz), XN = unpack2(xn), HN = unpack2(hn);
                float r0 = sig_fast(RZ.x), z0 = sig_fast(RZ.y);
                float n0 = tanh_fast(fmaf(r0, HN.x, XN.x));
                float o0 = fmaf(z0, h2v.x - n0, n0);
                float r1 = sig_fast(RZb.x), z1 = sig_fast(RZb.y);
                float n1 = tanh_fast(fmaf(r1, HN.y, XN.y));
                float o1 = fmaf(z1, h2v.y - n1, n1);
                s_h2[bo][lane][0] = o0;
                s_h2[bo][lane][1] = o1;
                float2 ov; ov.x = o0; ov.y = o1;
                *reinterpret_cast<float2*>(
                    out + (size_t)(k - 2) * (BB * 2) + (size_t)(blk * 32 + lane) * 2) = ov;
            }
        } else {
            // x prefetch: warps 12,13 load x[k+1] into s_x[bo]
            if (k + 1 < TT) {
                int t0 = ji * 32 + lane;
                const float* src = x + (size_t)(k + 1) * (BB * 5) + (size_t)blk * 160;
#pragma unroll
                for (int m = 0; m < 3; ++m) {
                    int t = t0 + m * 64;
                    if (t < 160) s_x[bo][t / 5][t % 5] = src[t];
                }
            }
        }

        __syncthreads();
    }
}

extern "C" void kernel_launch(void* const* d_in, const int* in_sizes, int n_in,
                              void* d_out, int out_size) {
    (void)in_sizes; (void)n_in; (void)out_size;
    const float* x = (const float*)d_in[0];

    pack_weights<<<4, 256>>>(
        (const float*)d_in[1], (const float*)d_in[2],
        (const float*)d_in[3], (const float*)d_in[4],
        (const float*)d_in[5], (const float*)d_in[6],
        (const float*)d_in[7], (const float*)d_in[8],
        (const float*)d_in[9], (const float*)d_in[10],
        (const float*)d_in[11], (const float*)d_in[12]);

    void* gp_addr = nullptr;
    cudaGetSymbolAddress(&gp_addr, g_pack);
    cudaMemcpyToSymbolAsync(CW, gp_addr, NPACK * sizeof(ull), 0,
                            cudaMemcpyDeviceToDevice, 0);

    gru_fused<<<BB / 32, 512>>>(x, (const ull*)gp_addr, (float*)d_out);
}

// round 7
// speedup vs baseline: 1.2606x; 1.0811x over previous
#include <cuda_runtime.h>
#include <cstddef>

#define TT 1024
#define BB 4096

typedef unsigned long long ull;

// ---------------- packed weight layout (ull = f32x2 pair) ----------------
// L0 jobs p=0..7 (units a=2p, b=2p+1; p=7 single):  base = p*68
//   +0  RZA[20]  (r_a,z_a) over [x(5), h0(15)]
//   +20 RZB[20]
//   +40 XN[6]    (n_a,n_b) over x(5) + pad
//   +46 HN[16]   (n_a,n_b) over h0(15) + pad
//   +62 B[4]     brz_a, brz_b, bxn, bhn      (66..67 pad)
// L1 jobs q=0..4 (a=2q,b=2q+1):  base = 544 + q*82
//   +0 RZA[26] over [h0(15), h1(10), pad]; +26 RZB[26]; +52 XN[16] over h0+pad;
//   +68 HN[10] over h1; +78 B[4]
// L2 job: base = 954
//   +0 RZA[12] over [h1(10), h2(2)]; +12 RZB[12]; +24 XN[10]; +34 HN[2]; +36 B[4]
// total 994 ull
#define L0BASE 0
#define L1BASE 544
#define L2BASE 954
#define NPACK 994

__device__ ull g_pack[1024];

__device__ __forceinline__ ull ffma2(ull a, ull b, ull c) {
    ull d;
    asm("fma.rn.f32x2 %0, %1, %2, %3;" : "=l"(d) : "l"(a), "l"(b), "l"(c));
    return d;
}
__device__ __forceinline__ ull fadd2(ull a, ull b) {
    ull d;
    asm("add.rn.f32x2 %0, %1, %2;" : "=l"(d) : "l"(a), "l"(b));
    return d;
}
__device__ __forceinline__ ull pack2(float lo, float hi) {
    ull d;
    asm("mov.b64 %0, {%1, %2};" : "=l"(d) : "f"(lo), "f"(hi));
    return d;
}
__device__ __forceinline__ float2 unpack2(ull v) {
    float2 f;
    asm("mov.b64 {%0, %1}, %2;" : "=f"(f.x), "=f"(f.y) : "l"(v));
    return f;
}
__device__ __forceinline__ float tanh_fast(float v) {
    float r;
    asm("tanh.approx.f32 %0, %1;" : "=f"(r) : "f"(v));
    return r;
}
__device__ __forceinline__ float sig_fast(float v) {
    return fmaf(0.5f, tanh_fast(0.5f * v), 0.5f);
}

// shared-memory packed dot (uniform LDS.128 weight loads, broadcast)
template <int C>
__device__ __forceinline__ ull dots(const ull* __restrict__ w, const ull* st, ull bias) {
    ull a0 = bias, a1 = 0ull;
    const ulonglong2* w2 = reinterpret_cast<const ulonglong2*>(w);
#pragma unroll
    for (int i = 0; i < C / 2; ++i) {
        ulonglong2 ww = w2[i];
        a0 = ffma2(ww.x, st[2 * i], a0);
        a1 = ffma2(ww.y, st[2 * i + 1], a1);
    }
    return fadd2(a0, a1);
}

// ---------------- pack kernel ----------------
__global__ void pack_weights(
    const float* __restrict__ wih0, const float* __restrict__ whh0,
    const float* __restrict__ bih0, const float* __restrict__ bhh0,
    const float* __restrict__ wih1, const float* __restrict__ whh1,
    const float* __restrict__ bih1, const float* __restrict__ bhh1,
    const float* __restrict__ wih2, const float* __restrict__ whh2,
    const float* __restrict__ bih2, const float* __restrict__ bhh2)
{
    int i = blockIdx.x * blockDim.x + threadIdx.x;
    if (i >= NPACK) return;
    float lo = 0.f, hi = 0.f;
    if (i < L1BASE) {
        int p = i / 68, r = i % 68;
        int a = 2 * p, b = 2 * p + 1;
        bool hb = (b < 15);
        if (r < 20) {
            int j = r;
            if (j < 5) { lo = wih0[a * 5 + j]; hi = wih0[(15 + a) * 5 + j]; }
            else       { int jj = j - 5; lo = whh0[a * 15 + jj]; hi = whh0[(15 + a) * 15 + jj]; }
        } else if (r < 40) {
            int j = r - 20;
            if (hb) {
                if (j < 5) { lo = wih0[b * 5 + j]; hi = wih0[(15 + b) * 5 + j]; }
                else       { int jj = j - 5; lo = whh0[b * 15 + jj]; hi = whh0[(15 + b) * 15 + jj]; }
            }
        } else if (r < 46) {
            int j = r - 40;
            if (j < 5) { lo = wih0[(30 + a) * 5 + j]; hi = hb ? wih0[(30 + b) * 5 + j] : 0.f; }
        } else if (r < 62) {
            int j = r - 46;
            if (j < 15) { lo = whh0[(30 + a) * 15 + j]; hi = hb ? whh0[(30 + b) * 15 + j] : 0.f; }
        } else if (r == 62) { lo = bih0[a] + bhh0[a]; hi = bih0[15 + a] + bhh0[15 + a]; }
        else if (r == 63) { if (hb) { lo = bih0[b] + bhh0[b]; hi = bih0[15 + b] + bhh0[15 + b]; } }
        else if (r == 64) { lo = bih0[30 + a]; hi = hb ? bih0[30 + b] : 0.f; }
        else if (r == 65) { lo = bhh0[30 + a]; hi = hb ? bhh0[30 + b] : 0.f; }
    } else if (i < L2BASE) {
        int t = i - L1BASE;
        int q = t / 82, r = t % 82;
        int a = 2 * q, b = 2 * q + 1;
        if (r < 26) {
            int j = r;
            if (j < 15)      { lo = wih1[a * 15 + j]; hi = wih1[(10 + a) * 15 + j]; }
            else if (j < 25) { int jj = j - 15; lo = whh1[a * 10 + jj]; hi = whh1[(10 + a) * 10 + jj]; }
        } else if (r < 52) {
            int j = r - 26;
            if (j < 15)      { lo = wih1[b * 15 + j]; hi = wih1[(10 + b) * 15 + j]; }
            else if (j < 25) { int jj = j - 15; lo = whh1[b * 10 + jj]; hi = whh1[(10 + b) * 10 + jj]; }
        } else if (r < 68) {
            int j = r - 52;
            if (j < 15) { lo = wih1[(20 + a) * 15 + j]; hi = wih1[(20 + b) * 15 + j]; }
        } else if (r < 78) {
            int j = r - 68;
            lo = whh1[(20 + a) * 10 + j]; hi = whh1[(20 + b) * 10 + j];
        } else if (r == 78) { lo = bih1[a] + bhh1[a]; hi = bih1[10 + a] + bhh1[10 + a]; }
        else if (r == 79) { lo = bih1[b] + bhh1[b]; hi = bih1[10 + b] + bhh1[10 + b]; }
        else if (r == 80) { lo = bih1[20 + a]; hi = bih1[20 + b]; }
        else              { lo = bhh1[20 + a]; hi = bhh1[20 + b]; }
    } else {
        int r = i - L2BASE;
        if (r < 12) {
            int j = r;
            if (j < 10) { lo = wih2[0 * 10 + j]; hi = wih2[2 * 10 + j]; }
            else        { int jj = j - 10; lo = whh2[0 * 2 + jj]; hi = whh2[2 * 2 + jj]; }
        } else if (r < 24) {
            int j = r - 12;
            if (j < 10) { lo = wih2[1 * 10 + j]; hi = wih2[3 * 10 + j]; }
            else        { int jj = j - 10; lo = whh2[1 * 2 + jj]; hi = whh2[3 * 2 + jj]; }
        } else if (r < 34) {
            int j = r - 24;
            lo = wih2[4 * 10 + j]; hi = wih2[5 * 10 + j];
        } else if (r < 36) {
            int j = r - 34;
            lo = whh2[4 * 2 + j]; hi = whh2[5 * 2 + j];
        } else if (r == 36) { lo = bih2[0] + bhh2[0]; hi = bih2[2] + bhh2[2]; }
        else if (r == 37) { lo = bih2[1] + bhh2[1]; hi = bih2[3] + bhh2[3]; }
        else if (r == 38) { lo = bih2[4]; hi = bih2[5]; }
        else              { lo = bhh2[4]; hi = bhh2[5]; }
    }
    ull v;
    asm("mov.b64 %0, {%1, %2};" : "=l"(v) : "f"(lo), "f"(hi));
    g_pack[i] = v;
}

// ---------------- main kernel ----------------
// grid 128, 512 threads = 16 warps per CTA of 32 batch elements.
// Skewed pipeline, 1 barrier/step: L0 computes h0[k], L1 h1[k-1], L2 h2[k-2].
// All weights in SMEM (broadcast LDS.128; no LDC port floor).
// Job types: 0 = L0 pair (ji=0..7), 1 = L1 pair (ji=0..3),
//            4 = L1 single unit 8, 5 = L1 single unit 9, 2 = L2, 3 = x-prefetch.
__global__ __launch_bounds__(512, 1) void gru_fused(
    const float* __restrict__ x, const ull* __restrict__ gp,
    float* __restrict__ out)
{
    __shared__ __align__(16) ull sW[NPACK + 2];
    __shared__ __align__(16) float s_x[2][32][12];  // x, cols 5..11 zero
    __shared__ __align__(16) float s_h0[2][32][20]; // h0, cols 15..19 zero
    __shared__ __align__(16) float s_h1[2][32][12]; // h1, cols 10..11 zero
    __shared__ __align__(16) float s_h2[2][32][4];  // h2, cols 2..3 zero

    const int tid = threadIdx.x;
    const int lane = tid & 31;
    const int w = tid >> 5;
    const int blk = blockIdx.x;

    for (int i = tid; i < NPACK; i += 512) sW[i] = gp[i];
    for (int i = tid; i < 2 * 32 * 20; i += 512) (&s_h0[0][0][0])[i] = 0.f;
    for (int i = tid; i < 2 * 32 * 12; i += 512) (&s_h1[0][0][0])[i] = 0.f;
    for (int i = tid; i < 2 * 32 * 12; i += 512) (&s_x[0][0][0])[i] = 0.f;
    for (int i = tid; i < 2 * 32 * 4; i += 512) (&s_h2[0][0][0])[i] = 0.f;
    if (tid < 160) s_x[0][tid / 5][tid % 5] = x[(size_t)blk * 160 + tid];
    __syncthreads();

    // job dispatch, SMSP (w&3) balanced:
    //   SMSP0: w0=L0p0  w4=L0p1  w8 =L1q0  w12=L1 single u8
    //   SMSP1: w1=L0p2  w5=L0p3  w9 =L1q1  w13=L1 single u9
    //   SMSP2: w2=L0p4  w6=L0p5  w10=L1q2  w14=L2
    //   SMSP3: w3=L0p6  w7=L0p7  w11=L1q3  w15=prefetch
    int jt, ji = 0;
    if (w < 8)       { jt = 0; ji = ((w & 3) << 1) | (w >> 2); } // p = 2*(w&3)+(w>>2)
    else if (w < 12) { jt = 1; ji = w - 8; }
    else if (w == 12) jt = 4;
    else if (w == 13) jt = 5;
    else if (w == 14) jt = 2;
    else              jt = 3;

    const ull* W0 = sW + ji * 68;                 // L0 base (jt==0)
    const ull* W1 = sW + L1BASE + ji * 82;        // L1 pair base (jt==1)
    const ull* W1s = sW + L1BASE + 4 * 82;        // L1 q=4 base (jt==4/5)
    const ull* W2 = sW + L2BASE;                  // L2 base

    for (int k = 0; k < TT + 2; ++k) {
        const int bi = k & 1;
        const int bo = bi ^ 1;

        if (jt == 0) {
            if (k < TT) {
                const int a = 2 * ji;
                const bool pair = (ji < 7);
                float xr[8], hr[16];
                const float4* xp4 = reinterpret_cast<const float4*>(&s_x[bi][lane][0]);
                const float4* hp4 = reinterpret_cast<const float4*>(&s_h0[bi][lane][0]);
#pragma unroll
                for (int i = 0; i < 2; ++i) {
                    float4 v = xp4[i];
                    xr[4 * i] = v.x; xr[4 * i + 1] = v.y; xr[4 * i + 2] = v.z; xr[4 * i + 3] = v.w;
                }
#pragma unroll
                for (int i = 0; i < 4; ++i) {
                    float4 v = hp4[i];
                    hr[4 * i] = v.x; hr[4 * i + 1] = v.y; hr[4 * i + 2] = v.z; hr[4 * i + 3] = v.w;
                }
                ull st[21];
#pragma unroll
                for (int j = 0; j < 5; ++j) st[j] = pack2(xr[j], xr[j]);
#pragma unroll
                for (int j = 0; j < 16; ++j) st[5 + j] = pack2(hr[j], hr[j]);
                ull arz = dots<20>(W0, st, W0[62]);
                ull brz = 0ull;
                if (pair) brz = dots<20>(W0 + 20, st, W0[63]);
                ull xn = dots<6>(W0 + 40, st, W0[64]);
                ull hn = dots<16>(W0 + 46, st + 5, W0[65]);
                float2 RZ = unpack2(arz), XN = unpack2(xn), HN = unpack2(hn);
                {
                    float r = sig_fast(RZ.x), z = sig_fast(RZ.y);
                    float n = tanh_fast(fmaf(r, HN.x, XN.x));
                    s_h0[bo][lane][a] = fmaf(z, hr[a] - n, n);
                }
                if (pair) {
                    float2 RZb = unpack2(brz);
                    float r = sig_fast(RZb.x), z = sig_fast(RZb.y);
                    float n = tanh_fast(fmaf(r, HN.y, XN.y));
                    s_h0[bo][lane][a + 1] = fmaf(z, hr[a + 1] - n, n);
                }
            }
        } else if (jt == 1) {
            if (k >= 1 && k <= TT) {
                const int a = 2 * ji;
                float h0r[16], h1r[12];
                const float4* hp4 = reinterpret_cast<const float4*>(&s_h0[bi][lane][0]);
                const float4* gp4 = reinterpret_cast<const float4*>(&s_h1[bi][lane][0]);
#pragma unroll
                for (int i = 0; i < 4; ++i) {
                    float4 v = hp4[i];
                    h0r[4 * i] = v.x; h0r[4 * i + 1] = v.y; h0r[4 * i + 2] = v.z; h0r[4 * i + 3] = v.w;
                }
#pragma unroll
                for (int i = 0; i < 3; ++i) {
                    float4 v = gp4[i];
                    h1r[4 * i] = v.x; h1r[4 * i + 1] = v.y; h1r[4 * i + 2] = v.z; h1r[4 * i + 3] = v.w;
                }
                ull st[26];
#pragma unroll
                for (int j = 0; j < 15; ++j) st[j] = pack2(h0r[j], h0r[j]);
#pragma unroll
                for (int j = 0; j < 10; ++j) st[15 + j] = pack2(h1r[j], h1r[j]);
                st[25] = 0ull;
                ull arz = dots<26>(W1, st, W1[78]);
                ull brz = dots<26>(W1 + 26, st, W1[79]);
                ull xn = dots<16>(W1 + 52, st, W1[80]);
                ull hn = dots<10>(W1 + 68, st + 15, W1[81]);
                float2 RZ = unpack2(arz), RZb = unpack2(brz), XN = unpack2(xn), HN = unpack2(hn);
                {
                    float r = sig_fast(RZ.x), z = sig_fast(RZ.y);
                    float n = tanh_fast(fmaf(r, HN.x, XN.x));
                    s_h1[bo][lane][a] = fmaf(z, h1r[a] - n, n);
                }
                {
                    float r = sig_fast(RZb.x), z = sig_fast(RZb.y);
                    float n = tanh_fast(fmaf(r, HN.y, XN.y));
                    s_h1[bo][lane][a + 1] = fmaf(z, h1r[a + 1] - n, n);
                }
            }
        } else if (jt == 4 || jt == 5) {
            // L1 single-unit jobs for units 8 (jt==4) / 9 (jt==5)
            if (k >= 1 && k <= TT) {
                float h0r[16], h1r[12];
                const float4* hp4 = reinterpret_cast<const float4*>(&s_h0[bi][lane][0]);
                const float4* gp4 = reinterpret_cast<const float4*>(&s_h1[bi][lane][0]);
#pragma unroll
                for (int i = 0; i < 4; ++i) {
                    float4 v = hp4[i];
                    h0r[4 * i] = v.x; h0r[4 * i + 1] = v.y; h0r[4 * i + 2] = v.z; h0r[4 * i + 3] = v.w;
                }
#pragma unroll
                for (int i = 0; i < 3; ++i) {
                    float4 v = gp4[i];
                    h1r[4 * i] = v.x; h1r[4 * i + 1] = v.y; h1r[4 * i + 2] = v.z; h1r[4 * i + 3] = v.w;
                }
                ull st[26];
#pragma unroll
                for (int j = 0; j < 15; ++j) st[j] = pack2(h0r[j], h0r[j]);
#pragma unroll
                for (int j = 0; j < 10; ++j) st[15 + j] = pack2(h1r[j], h1r[j]);
                st[25] = 0ull;
                const bool isA = (jt == 4);
                ull rz = isA ? dots<26>(W1s, st, W1s[78])
                             : dots<26>(W1s + 26, st, W1s[79]);
                ull xn = dots<16>(W1s + 52, st, W1s[80]);
                ull hn = dots<10>(W1s + 68, st + 15, W1s[81]);
                float2 RZ = unpack2(rz), XN = unpack2(xn), HN = unpack2(hn);
                float xnv = isA ? XN.x : XN.y;
                float hnv = isA ? HN.x : HN.y;
                int u = isA ? 8 : 9;
                float r = sig_fast(RZ.x), z = sig_fast(RZ.y);
                float n = tanh_fast(fmaf(r, hnv, xnv));
                s_h1[bo][lane][u] = fmaf(z, h1r[u] - n, n);
            }
        } else if (jt == 2) {
            if (k >= 2) {
                float h1r[12];
                const float4* gp4 = reinterpret_cast<const float4*>(&s_h1[bi][lane][0]);
#pragma unroll
                for (int i = 0; i < 3; ++i) {
                    float4 v = gp4[i];
                    h1r[4 * i] = v.x; h1r[4 * i + 1] = v.y; h1r[4 * i + 2] = v.z; h1r[4 * i + 3] = v.w;
                }
                float2 h2v = *reinterpret_cast<const float2*>(&s_h2[bi][lane][0]);
                ull st[12];
#pragma unroll
                for (int j = 0; j < 10; ++j) st[j] = pack2(h1r[j], h1r[j]);
                st[10] = pack2(h2v.x, h2v.x);
                st[11] = pack2(h2v.y, h2v.y);
                ull arz = dots<12>(W2, st, W2[36]);
                ull brz = dots<12>(W2 + 12, st, W2[37]);
                ull xn = dots<10>(W2 + 24, st, W2[38]);
                ull hn = dots<2>(W2 + 34, st + 10, W2[39]);
                float2 RZ = unpack2(arz), RZb = unpack2(brz), XN = unpack2(xn), HN = unpack2(hn);
                float r0 = sig_fast(RZ.x), z0 = sig_fast(RZ.y);
                float n0 = tanh_fast(fmaf(r0, HN.x, XN.x));
                float o0 = fmaf(z0, h2v.x - n0, n0);
                float r1 = sig_fast(RZb.x), z1 = sig_fast(RZb.y);
                float n1 = tanh_fast(fmaf(r1, HN.y, XN.y));
                float o1 = fmaf(z1, h2v.y - n1, n1);
                s_h2[bo][lane][0] = o0;
                s_h2[bo][lane][1] = o1;
                float2 ov; ov.x = o0; ov.y = o1;
                *reinterpret_cast<float2*>(
                    out + (size_t)(k - 2) * (BB * 2) + (size_t)(blk * 32 + lane) * 2) = ov;
            }
        } else {
            // x prefetch: warp 15 loads x[k+1] into s_x[bo]
            if (k + 1 < TT) {
                const float* src = x + (size_t)(k + 1) * (BB * 5) + (size_t)blk * 160;
#pragma unroll
                for (int m = 0; m < 5; ++m) {
                    int t = lane + m * 32;
                    s_x[bo][t / 5][t % 5] = src[t];
                }
            }
        }

        __syncthreads();
    }
}

extern "C" void kernel_launch(void* const* d_in, const int* in_sizes, int n_in,
                              void* d_out, int out_size) {
    (void)in_sizes; (void)n_in; (void)out_size;
    const float* x = (const float*)d_in[0];

    pack_weights<<<4, 256>>>(
        (const float*)d_in[1], (const float*)d_in[2],
        (const float*)d_in[3], (const float*)d_in[4],
        (const float*)d_in[5], (const float*)d_in[6],
        (const float*)d_in[7], (const float*)d_in[8],
        (const float*)d_in[9], (const float*)d_in[10],
        (const float*)d_in[11], (const float*)d_in[12]);

    void* gp_addr = nullptr;
    cudaGetSymbolAddress(&gp_addr, g_pack);

    gru_fused<<<BB / 32, 512>>>(x, (const ull*)gp_addr, (float*)d_out);
}